// round 5
// baseline (speedup 1.0000x reference)
#include <cuda_runtime.h>
#include <cuda_bf16.h>
#include <cstdint>

#define NPIX 4096
#define CIN  512
#define B    4

__device__ __align__(16) __nv_bfloat16 g_xT[(size_t)B * NPIX * CIN];   // [b][n][c]
__device__ __align__(16) __nv_bfloat16 g_q [(size_t)B * NPIX * 64];    // [b][n][d]
__device__ __align__(16) __nv_bfloat16 g_k [(size_t)B * NPIX * 64];    // [b][n][d]
__device__ __align__(16) __nv_bfloat16 g_v [(size_t)B * NPIX * CIN];   // [b][n][c]
__device__ __align__(16) __nv_bfloat16 g_wqk[128 * CIN];               // [q64;k64][c]
__device__ __align__(16) __nv_bfloat16 g_wv [CIN * CIN];               // [o][c]

// ------------------------------ helpers -----------------------------------
__device__ __forceinline__ uint32_t smem_u32(const void* p) {
    uint32_t a;
    asm("{ .reg .u64 t; cvta.to.shared.u64 t, %1; cvt.u32.u64 %0, t; }" : "=r"(a) : "l"(p));
    return a;
}
__device__ __forceinline__ void ldsm_x4(uint32_t* r, uint32_t a) {
    asm volatile("ldmatrix.sync.aligned.m8n8.x4.shared.b16 {%0,%1,%2,%3}, [%4];"
        : "=r"(r[0]), "=r"(r[1]), "=r"(r[2]), "=r"(r[3]) : "r"(a));
}
__device__ __forceinline__ void ldsm_x4t(uint32_t* r, uint32_t a) {
    asm volatile("ldmatrix.sync.aligned.m8n8.x4.trans.shared.b16 {%0,%1,%2,%3}, [%4];"
        : "=r"(r[0]), "=r"(r[1]), "=r"(r[2]), "=r"(r[3]) : "r"(a));
}
__device__ __forceinline__ void mma_bf16(float* d, const uint32_t* a, const uint32_t* b) {
    asm volatile("mma.sync.aligned.m16n8k16.row.col.f32.bf16.bf16.f32 "
        "{%0,%1,%2,%3},{%4,%5,%6,%7},{%8,%9},{%0,%1,%2,%3};"
        : "+f"(d[0]), "+f"(d[1]), "+f"(d[2]), "+f"(d[3])
        : "r"(a[0]), "r"(a[1]), "r"(a[2]), "r"(a[3]), "r"(b[0]), "r"(b[1]));
}
__device__ __forceinline__ void cp16(uint32_t dst, const void* src) {
    asm volatile("cp.async.cg.shared.global [%0], [%1], 16;" :: "r"(dst), "l"(src));
}
#define CP_COMMIT() asm volatile("cp.async.commit_group;" ::: "memory")
#define CP_WAIT0()  asm volatile("cp.async.wait_group 0;" ::: "memory")
__device__ __forceinline__ uint32_t pack_bf2(float lo, float hi) {
    uint32_t u;
    asm("cvt.rn.bf16x2.f32 %0, %1, %2;" : "=r"(u) : "f"(hi), "f"(lo));
    return u;
}

// -------------------------- prep kernels ----------------------------------
__global__ void convert_w_kernel(const float* __restrict__ Wq, const float* __restrict__ Wk,
                                 const float* __restrict__ Wv) {
    int i = blockIdx.x * 256 + threadIdx.x;
    if (i < 64 * CIN) g_wqk[i] = __float2bfloat16(Wq[i]);
    else if (i < 128 * CIN) g_wqk[i] = __float2bfloat16(Wk[i - 64 * CIN]);
    else if (i < 128 * CIN + CIN * CIN) g_wv[i - 128 * CIN] = __float2bfloat16(Wv[i - 128 * CIN]);
}

__global__ __launch_bounds__(256)
void transpose_x_kernel(const float* __restrict__ x) {
    __shared__ float s[64][65];
    const int n0 = blockIdx.x * 64, c0 = blockIdx.y * 64, b = blockIdx.z;
    const float* xb = x + ((size_t)b * CIN + c0) * NPIX + n0;
    for (int i = threadIdx.x; i < 64 * 64; i += 256) {
        int c = i >> 6, n = i & 63;
        s[c][n] = xb[(size_t)c * NPIX + n];
    }
    __syncthreads();
    __nv_bfloat16* dst = g_xT + ((size_t)b * NPIX + n0) * CIN + c0;
    for (int i = threadIdx.x; i < 64 * 32; i += 256) {
        int n = i >> 5, c2 = (i & 31) * 2;
        *reinterpret_cast<__nv_bfloat162*>(dst + (size_t)n * CIN + c2) =
            __float22bfloat162_rn(make_float2(s[c2][n], s[c2 + 1][n]));
    }
}

// ---------------- fused proj: C[n(128), out(128)] = xT . W^T --------------
// chunk 0: out = [q64|k64]; chunks 1-4: out = v[(chunk-1)*128 ...]
// smem: A 2x18432, B 2x18432 (rows padded to 144B)
__global__ __launch_bounds__(256)
void proj_qkv_kernel(const float* __restrict__ bq, const float* __restrict__ bk,
                     const float* __restrict__ bv) {
    extern __shared__ char dsm[];
    const uint32_t sb = smem_u32(dsm);
    const uint32_t SA = sb, SB = sb + 36864;
    const int tid = threadIdx.x, wid = tid >> 5, lane = tid & 31;
    const int n0 = blockIdx.x * 128, chunk = blockIdx.y, b = blockIdx.z;
    const __nv_bfloat16* gA = g_xT + ((size_t)b * NPIX + n0) * CIN;
    const __nv_bfloat16* gB = (chunk == 0) ? g_wqk : (g_wv + (size_t)(chunk - 1) * 128 * CIN);

    auto ldA = [&](uint32_t dst, int kk) {
        for (int i = tid; i < 1024; i += 256) {
            int r = i >> 3, s = i & 7;
            cp16(dst + r * 144 + s * 16, gA + (size_t)r * CIN + kk * 64 + s * 8);
        }
    };
    auto ldB = [&](uint32_t dst, int kk) {
        for (int i = tid; i < 1024; i += 256) {
            int r = i >> 3, s = i & 7;
            cp16(dst + r * 144 + s * 16, gB + (size_t)r * CIN + kk * 64 + s * 8);
        }
    };
    ldA(SA, 0); ldB(SB, 0); CP_COMMIT(); CP_WAIT0(); __syncthreads();

    const int ar = (lane & 7) + ((lane >> 3) & 1) * 8, ak = ((lane >> 4) & 1) * 8;
    const int bn = ((lane >> 4) & 1) * 8 + (lane & 7), bk2 = ((lane >> 3) & 1) * 8;
    float o[16][4] = {};

    for (int kk = 0; kk < 8; kk++) {
        const int buf = kk & 1;
        if (kk < 7) { ldA(SA + (buf ^ 1) * 18432, kk + 1); ldB(SB + (buf ^ 1) * 18432, kk + 1); CP_COMMIT(); }
        const uint32_t Ab = SA + buf * 18432 + (16 * wid + ar) * 144 + ak * 2;
        const uint32_t Bb = SB + buf * 18432;
        uint32_t qa[4][4];
        #pragma unroll
        for (int kc = 0; kc < 4; kc++) ldsm_x4(qa[kc], Ab + kc * 32);
        #pragma unroll
        for (int ot2 = 0; ot2 < 8; ot2++) {
            #pragma unroll
            for (int kc = 0; kc < 4; kc++) {
                uint32_t br[4];
                ldsm_x4(br, Bb + (ot2 * 16 + bn) * 144 + (kc * 16 + bk2) * 2);
                mma_bf16(o[ot2 * 2],     qa[kc], br);
                mma_bf16(o[ot2 * 2 + 1], qa[kc], br + 2);
            }
        }
        if (kk < 7) CP_WAIT0();
        __syncthreads();
    }

    const int r0 = 16 * wid + (lane >> 2);
    if (chunk == 0) {
        #pragma unroll
        for (int ot = 0; ot < 16; ot++) {
            int oc = ot * 8 + (lane & 3) * 2;
            const float* bias = (oc < 64) ? bq : bk;
            int oo = oc & 63;
            float b0 = __ldg(bias + oo), b1 = __ldg(bias + oo + 1);
            __nv_bfloat16* base = (oc < 64) ? g_q : g_k;
            uint32_t* d0 = reinterpret_cast<uint32_t*>(base + ((size_t)b * NPIX + n0 + r0) * 64 + oo);
            uint32_t* d1 = reinterpret_cast<uint32_t*>(base + ((size_t)b * NPIX + n0 + r0 + 8) * 64 + oo);
            *d0 = pack_bf2(o[ot][0] + b0, o[ot][1] + b1);
            *d1 = pack_bf2(o[ot][2] + b0, o[ot][3] + b1);
        }
    } else {
        const int c0 = (chunk - 1) * 128;
        #pragma unroll
        for (int ot = 0; ot < 16; ot++) {
            int c = c0 + ot * 8 + (lane & 3) * 2;
            float b0 = __ldg(bv + c), b1 = __ldg(bv + c + 1);
            uint32_t* d0 = reinterpret_cast<uint32_t*>(g_v + ((size_t)b * NPIX + n0 + r0) * CIN + c);
            uint32_t* d1 = reinterpret_cast<uint32_t*>(g_v + ((size_t)b * NPIX + n0 + r0 + 8) * CIN + c);
            *d0 = pack_bf2(o[ot][0] + b0, o[ot][1] + b1);
            *d1 = pack_bf2(o[ot][2] + b0, o[ot][3] + b1);
        }
    }
}

// --------------------------- fused attention ------------------------------
// CTA: 128 m x 256 c-half x b. 8 warps = 4 m-slots (32 rows) x 2 c-slots (128 c).
// smem: Q 18432 | K 2x18432 | V 2x67584 = 190464; epilogue reuses as f32[128][257].
__global__ __launch_bounds__(256, 1)
void attn_kernel(const float* __restrict__ x, float* __restrict__ out) {
    extern __shared__ char dsm[];
    const uint32_t sb = smem_u32(dsm);
    const uint32_t SQ = sb, SK = sb + 18432, SV = sb + 55296;
    const int tid = threadIdx.x, wid = tid >> 5, lane = tid & 31;
    const int mslot = wid & 3, cw = wid >> 2;
    const int m0 = blockIdx.x * 128, chalf = blockIdx.y, b = blockIdx.z;

    const __nv_bfloat16* gQ = g_q + ((size_t)b * NPIX + m0) * 64;
    const __nv_bfloat16* gK = g_k + (size_t)b * NPIX * 64;
    const __nv_bfloat16* gV = g_v + (size_t)b * NPIX * CIN + chalf * 256;

    auto ldK = [&](uint32_t dst, int jj) {
        const __nv_bfloat16* src = gK + (size_t)jj * 128 * 64;
        for (int i = tid; i < 1024; i += 256) {
            int r = i >> 3, s = i & 7;
            cp16(dst + r * 144 + s * 16, src + (size_t)r * 64 + s * 8);
        }
    };
    auto ldV = [&](uint32_t dst, int jj) {
        const __nv_bfloat16* src = gV + (size_t)jj * 128 * CIN;
        for (int i = tid; i < 4096; i += 256) {
            int r = i >> 5, s = i & 31;
            cp16(dst + r * 528 + s * 16, src + (size_t)r * CIN + s * 8);
        }
    };
    for (int i = tid; i < 1024; i += 256) {
        int r = i >> 3, s = i & 7;
        cp16(SQ + r * 144 + s * 16, gQ + (size_t)r * 64 + s * 8);
    }
    ldK(SK, 0); ldV(SV, 0);
    CP_COMMIT(); CP_WAIT0(); __syncthreads();

    const int ar = (lane & 7) + ((lane >> 3) & 1) * 8, ak = ((lane >> 4) & 1) * 8;
    const int bn = ((lane >> 4) & 1) * 8 + (lane & 7), bk2 = ((lane >> 3) & 1) * 8;
    const int vn = ((lane >> 3) & 1) * 8 + (lane & 7), vc = ((lane >> 4) & 1) * 8;

    // Q fragments for this warp's 2 m-tiles (hoisted; Q smem never overwritten)
    uint32_t qa[2][4][4];
    #pragma unroll
    for (int mt = 0; mt < 2; mt++) {
        const uint32_t Ab = SQ + (mslot * 32 + mt * 16 + ar) * 144 + ak * 2;
        #pragma unroll
        for (int kc = 0; kc < 4; kc++) ldsm_x4(qa[mt][kc], Ab + kc * 32);
    }

    float o[2][16][4] = {};
    float rs[2][2] = {};

    for (int j = 0; j < 32; j++) {
        const int buf = j & 1;
        if (j < 31) { ldK(SK + (buf ^ 1) * 18432, j + 1); ldV(SV + (buf ^ 1) * 67584, j + 1); CP_COMMIT(); }
        const uint32_t Kb = SK + buf * 18432, Vb = SV + buf * 67584;

        #pragma unroll
        for (int nt = 0; nt < 8; nt++) {
            // S = Q.K^T for both m-tiles (K fragment shared)
            float s[2][8] = {};
            #pragma unroll
            for (int kc = 0; kc < 4; kc++) {
                uint32_t br[4];
                ldsm_x4(br, Kb + (nt * 16 + bn) * 144 + (kc * 16 + bk2) * 2);
                #pragma unroll
                for (int mt = 0; mt < 2; mt++) {
                    mma_bf16(s[mt],     qa[mt][kc], br);
                    mma_bf16(s[mt] + 4, qa[mt][kc], br + 2);
                }
            }
            // exp + pack P fragments (A-layout for the O mma)
            uint32_t pa[2][4];
            #pragma unroll
            for (int mt = 0; mt < 2; mt++) {
                #pragma unroll
                for (int t = 0; t < 8; t++) s[mt][t] = __expf(s[mt][t]);
                rs[mt][0] += s[mt][0] + s[mt][1] + s[mt][4] + s[mt][5];
                rs[mt][1] += s[mt][2] + s[mt][3] + s[mt][6] + s[mt][7];
                pa[mt][0] = pack_bf2(s[mt][0], s[mt][1]);
                pa[mt][1] = pack_bf2(s[mt][2], s[mt][3]);
                pa[mt][2] = pack_bf2(s[mt][4], s[mt][5]);
                pa[mt][3] = pack_bf2(s[mt][6], s[mt][7]);
            }
            // O += P.V^T over this warp's 128-c slice
            #pragma unroll
            for (int ct = 0; ct < 8; ct++) {
                uint32_t vr[4];
                ldsm_x4t(vr, Vb + (nt * 16 + vn) * 528 + (cw * 128 + ct * 16 + vc) * 2);
                #pragma unroll
                for (int mt = 0; mt < 2; mt++) {
                    mma_bf16(o[mt][ct * 2],     pa[mt], vr);
                    mma_bf16(o[mt][ct * 2 + 1], pa[mt], vr + 2);
                }
            }
        }
        if (j < 31) CP_WAIT0();
        __syncthreads();
    }

    // row-sum reduce across quad lanes
    float inv[2][2];
    #pragma unroll
    for (int mt = 0; mt < 2; mt++)
        #pragma unroll
        for (int h = 0; h < 2; h++) {
            float r = rs[mt][h];
            r += __shfl_xor_sync(0xffffffffu, r, 1);
            r += __shfl_xor_sync(0xffffffffu, r, 2);
            inv[mt][h] = 1.0f / r;
        }

    // epilogue: transpose via smem (reuse), out[b][c][m] = O/sum + x
    float* epi = reinterpret_cast<float*>(dsm);
    #pragma unroll
    for (int mt = 0; mt < 2; mt++) {
        const int r = mslot * 32 + mt * 16 + (lane >> 2);
        #pragma unroll
        for (int ct = 0; ct < 16; ct++) {
            int c = cw * 128 + ct * 8 + (lane & 3) * 2;
            epi[r * 257 + c]           = o[mt][ct][0] * inv[mt][0];
            epi[r * 257 + c + 1]       = o[mt][ct][1] * inv[mt][0];
            epi[(r + 8) * 257 + c]     = o[mt][ct][2] * inv[mt][1];
            epi[(r + 8) * 257 + c + 1] = o[mt][ct][3] * inv[mt][1];
        }
    }
    __syncthreads();
    const float* xb = x + (size_t)b * CIN * NPIX;
    float* ob = out + (size_t)b * CIN * NPIX;
    for (int i = tid; i < 256 * 128; i += 256) {
        int c = i >> 7, m = i & 127;
        size_t gidx = (size_t)(chalf * 256 + c) * NPIX + m0 + m;
        ob[gidx] = epi[m * 257 + c] + xb[gidx];
    }
}

// ---------------------------------------------------------------------------
extern "C" void kernel_launch(void* const* d_in, const int* in_sizes, int n_in,
                              void* d_out, int out_size)
{
    const float* x  = (const float*)d_in[0];
    const float* Wq = (const float*)d_in[1];
    const float* bq = (const float*)d_in[2];
    const float* Wk = (const float*)d_in[3];
    const float* bk = (const float*)d_in[4];
    const float* Wv = (const float*)d_in[5];
    const float* bv = (const float*)d_in[6];
    float* out = (float*)d_out;

    cudaFuncSetAttribute(proj_qkv_kernel, cudaFuncAttributeMaxDynamicSharedMemorySize, 73728);
    cudaFuncSetAttribute(attn_kernel,     cudaFuncAttributeMaxDynamicSharedMemorySize, 190464);

    convert_w_kernel<<<1280, 256>>>(Wq, Wk, Wv);
    transpose_x_kernel<<<dim3(NPIX / 64, CIN / 64, B), 256>>>(x);
    proj_qkv_kernel<<<dim3(NPIX / 128, 5, B), 256, 73728>>>(bq, bk, bv);
    attn_kernel<<<dim3(NPIX / 128, 2, B), 256, 190464>>>(x, out);
}

// round 6
// speedup vs baseline: 1.1650x; 1.1650x over previous
#include <cuda_runtime.h>
#include <cuda_bf16.h>
#include <cstdint>

#define NPIX 4096
#define CIN  512
#define B    4

__device__ __align__(16) __nv_bfloat16 g_xT[(size_t)B * NPIX * CIN];   // [b][n][c]
__device__ __align__(16) __nv_bfloat16 g_q [(size_t)B * NPIX * 64];    // [b][n][d]
__device__ __align__(16) __nv_bfloat16 g_k [(size_t)B * NPIX * 64];    // [b][n][d]
__device__ __align__(16) __nv_bfloat16 g_v [(size_t)B * NPIX * CIN];   // [b][n][c]
__device__ __align__(16) __nv_bfloat16 g_wqk[128 * CIN];               // [q64;k64][c]
__device__ __align__(16) __nv_bfloat16 g_wv [CIN * CIN];               // [o][c]

// ------------------------------ helpers -----------------------------------
__device__ __forceinline__ uint32_t smem_u32(const void* p) {
    uint32_t a;
    asm("{ .reg .u64 t; cvta.to.shared.u64 t, %1; cvt.u32.u64 %0, t; }" : "=r"(a) : "l"(p));
    return a;
}
__device__ __forceinline__ void ldsm_x4(uint32_t* r, uint32_t a) {
    asm volatile("ldmatrix.sync.aligned.m8n8.x4.shared.b16 {%0,%1,%2,%3}, [%4];"
        : "=r"(r[0]), "=r"(r[1]), "=r"(r[2]), "=r"(r[3]) : "r"(a));
}
__device__ __forceinline__ void ldsm_x4t(uint32_t* r, uint32_t a) {
    asm volatile("ldmatrix.sync.aligned.m8n8.x4.trans.shared.b16 {%0,%1,%2,%3}, [%4];"
        : "=r"(r[0]), "=r"(r[1]), "=r"(r[2]), "=r"(r[3]) : "r"(a));
}
__device__ __forceinline__ void mma_bf16(float* d, const uint32_t* a, const uint32_t* b) {
    asm volatile("mma.sync.aligned.m16n8k16.row.col.f32.bf16.bf16.f32 "
        "{%0,%1,%2,%3},{%4,%5,%6,%7},{%8,%9},{%0,%1,%2,%3};"
        : "+f"(d[0]), "+f"(d[1]), "+f"(d[2]), "+f"(d[3])
        : "r"(a[0]), "r"(a[1]), "r"(a[2]), "r"(a[3]), "r"(b[0]), "r"(b[1]));
}
__device__ __forceinline__ void cp16(uint32_t dst, const void* src) {
    asm volatile("cp.async.cg.shared.global [%0], [%1], 16;" :: "r"(dst), "l"(src));
}
#define CP_COMMIT() asm volatile("cp.async.commit_group;" ::: "memory")
#define CP_WAIT0()  asm volatile("cp.async.wait_group 0;" ::: "memory")
__device__ __forceinline__ uint32_t pack_bf2(float lo, float hi) {
    uint32_t u;
    asm("cvt.rn.bf16x2.f32 %0, %1, %2;" : "=r"(u) : "f"(hi), "f"(lo));
    return u;
}

// -------------------------- prep kernels ----------------------------------
__global__ void convert_w_kernel(const float* __restrict__ Wq, const float* __restrict__ Wk,
                                 const float* __restrict__ Wv) {
    int i = blockIdx.x * 256 + threadIdx.x;
    if (i < 64 * CIN) g_wqk[i] = __float2bfloat16(Wq[i]);
    else if (i < 128 * CIN) g_wqk[i] = __float2bfloat16(Wk[i - 64 * CIN]);
    else if (i < 128 * CIN + CIN * CIN) g_wv[i - 128 * CIN] = __float2bfloat16(Wv[i - 128 * CIN]);
}

__global__ __launch_bounds__(256)
void transpose_x_kernel(const float* __restrict__ x) {
    __shared__ float s[64][65];
    const int n0 = blockIdx.x * 64, c0 = blockIdx.y * 64, b = blockIdx.z;
    const float* xb = x + ((size_t)b * CIN + c0) * NPIX + n0;
    for (int i = threadIdx.x; i < 64 * 64; i += 256) {
        int c = i >> 6, n = i & 63;
        s[c][n] = xb[(size_t)c * NPIX + n];
    }
    __syncthreads();
    __nv_bfloat16* dst = g_xT + ((size_t)b * NPIX + n0) * CIN + c0;
    for (int i = threadIdx.x; i < 64 * 32; i += 256) {
        int n = i >> 5, c2 = (i & 31) * 2;
        *reinterpret_cast<__nv_bfloat162*>(dst + (size_t)n * CIN + c2) =
            __float22bfloat162_rn(make_float2(s[c2][n], s[c2 + 1][n]));
    }
}

// ---------------- fused proj: C[n(128), out(128)] = xT . W^T --------------
// chunk 0: out = [q64|k64]; chunks 1-4: out = v[(chunk-1)*128 ...]
__global__ __launch_bounds__(256)
void proj_qkv_kernel(const float* __restrict__ bq, const float* __restrict__ bk,
                     const float* __restrict__ bv) {
    extern __shared__ char dsm[];
    const uint32_t sb = smem_u32(dsm);
    const uint32_t SA = sb, SB = sb + 36864;
    const int tid = threadIdx.x, wid = tid >> 5, lane = tid & 31;
    const int n0 = blockIdx.x * 128, chunk = blockIdx.y, b = blockIdx.z;
    const __nv_bfloat16* gA = g_xT + ((size_t)b * NPIX + n0) * CIN;
    const __nv_bfloat16* gB = (chunk == 0) ? g_wqk : (g_wv + (size_t)(chunk - 1) * 128 * CIN);

    auto ldA = [&](uint32_t dst, int kk) {
        for (int i = tid; i < 1024; i += 256) {
            int r = i >> 3, s = i & 7;
            cp16(dst + r * 144 + s * 16, gA + (size_t)r * CIN + kk * 64 + s * 8);
        }
    };
    auto ldB = [&](uint32_t dst, int kk) {
        for (int i = tid; i < 1024; i += 256) {
            int r = i >> 3, s = i & 7;
            cp16(dst + r * 144 + s * 16, gB + (size_t)r * CIN + kk * 64 + s * 8);
        }
    };
    ldA(SA, 0); ldB(SB, 0); CP_COMMIT(); CP_WAIT0(); __syncthreads();

    const int ar = (lane & 7) + ((lane >> 3) & 1) * 8, ak = ((lane >> 4) & 1) * 8;
    const int bn = ((lane >> 4) & 1) * 8 + (lane & 7), bk2 = ((lane >> 3) & 1) * 8;
    float o[16][4] = {};

    for (int kk = 0; kk < 8; kk++) {
        const int buf = kk & 1;
        if (kk < 7) { ldA(SA + (buf ^ 1) * 18432, kk + 1); ldB(SB + (buf ^ 1) * 18432, kk + 1); CP_COMMIT(); }
        const uint32_t Ab = SA + buf * 18432 + (16 * wid + ar) * 144 + ak * 2;
        const uint32_t Bb = SB + buf * 18432;
        uint32_t qa[4][4];
        #pragma unroll
        for (int kc = 0; kc < 4; kc++) ldsm_x4(qa[kc], Ab + kc * 32);
        #pragma unroll
        for (int ot2 = 0; ot2 < 8; ot2++) {
            #pragma unroll
            for (int kc = 0; kc < 4; kc++) {
                uint32_t br[4];
                ldsm_x4(br, Bb + (ot2 * 16 + bn) * 144 + (kc * 16 + bk2) * 2);
                mma_bf16(o[ot2 * 2],     qa[kc], br);
                mma_bf16(o[ot2 * 2 + 1], qa[kc], br + 2);
            }
        }
        if (kk < 7) CP_WAIT0();
        __syncthreads();
    }

    const int r0 = 16 * wid + (lane >> 2);
    if (chunk == 0) {
        #pragma unroll
        for (int ot = 0; ot < 16; ot++) {
            int oc = ot * 8 + (lane & 3) * 2;
            const float* bias = (oc < 64) ? bq : bk;
            int oo = oc & 63;
            float b0 = __ldg(bias + oo), b1 = __ldg(bias + oo + 1);
            __nv_bfloat16* base = (oc < 64) ? g_q : g_k;
            uint32_t* d0 = reinterpret_cast<uint32_t*>(base + ((size_t)b * NPIX + n0 + r0) * 64 + oo);
            uint32_t* d1 = reinterpret_cast<uint32_t*>(base + ((size_t)b * NPIX + n0 + r0 + 8) * 64 + oo);
            *d0 = pack_bf2(o[ot][0] + b0, o[ot][1] + b1);
            *d1 = pack_bf2(o[ot][2] + b0, o[ot][3] + b1);
        }
    } else {
        const int c0 = (chunk - 1) * 128;
        #pragma unroll
        for (int ot = 0; ot < 16; ot++) {
            int c = c0 + ot * 8 + (lane & 3) * 2;
            float b0 = __ldg(bv + c), b1 = __ldg(bv + c + 1);
            uint32_t* d0 = reinterpret_cast<uint32_t*>(g_v + ((size_t)b * NPIX + n0 + r0) * CIN + c);
            uint32_t* d1 = reinterpret_cast<uint32_t*>(g_v + ((size_t)b * NPIX + n0 + r0 + 8) * CIN + c);
            *d0 = pack_bf2(o[ot][0] + b0, o[ot][1] + b1);
            *d1 = pack_bf2(o[ot][2] + b0, o[ot][3] + b1);
        }
    }
}

// --------------------------- fused attention ------------------------------
// CTA: 128 m x 128 c-quarter x b (grid 32x4x4 = 512). 8 warps, 16 m-rows each.
// smem 104 KB: [SQK1 18432 | SK0 18432 | SV 2x34816]. Q smem becomes K buf 1
// after Q fragments are hoisted. 2 CTAs/SM via __launch_bounds__(256,2).
// Epilogue reuses smem as f32 epi[128][129].
__global__ __launch_bounds__(256, 2)
void attn_kernel(const float* __restrict__ x, float* __restrict__ out) {
    extern __shared__ char dsm[];
    const uint32_t sb = smem_u32(dsm);
    const uint32_t SQK1 = sb, SK0 = sb + 18432, SV = sb + 36864;
    const int tid = threadIdx.x, wid = tid >> 5, lane = tid & 31;
    const int m0 = blockIdx.x * 128, cq = blockIdx.y, b = blockIdx.z;

    const __nv_bfloat16* gQ = g_q + ((size_t)b * NPIX + m0) * 64;
    const __nv_bfloat16* gK = g_k + (size_t)b * NPIX * 64;
    const __nv_bfloat16* gV = g_v + (size_t)b * NPIX * CIN + cq * 128;

    auto ldK = [&](uint32_t dst, int jj) {
        const __nv_bfloat16* src = gK + (size_t)jj * 128 * 64;
        for (int i = tid; i < 1024; i += 256) {
            int r = i >> 3, s = i & 7;
            cp16(dst + r * 144 + s * 16, src + (size_t)r * 64 + s * 8);
        }
    };
    auto ldV = [&](uint32_t dst, int jj) {
        const __nv_bfloat16* src = gV + (size_t)jj * 128 * CIN;
        for (int i = tid; i < 2048; i += 256) {
            int r = i >> 4, s = i & 15;
            cp16(dst + r * 272 + s * 16, src + (size_t)r * CIN + s * 8);
        }
    };
    // prologue: Q (into SQK1), K0, V0
    for (int i = tid; i < 1024; i += 256) {
        int r = i >> 3, s = i & 7;
        cp16(SQK1 + r * 144 + s * 16, gQ + (size_t)r * 64 + s * 8);
    }
    ldK(SK0, 0); ldV(SV, 0);
    CP_COMMIT(); CP_WAIT0(); __syncthreads();

    const int ar = (lane & 7) + ((lane >> 3) & 1) * 8, ak = ((lane >> 4) & 1) * 8;
    const int bn = ((lane >> 4) & 1) * 8 + (lane & 7), bk2 = ((lane >> 3) & 1) * 8;
    const int vn = ((lane >> 3) & 1) * 8 + (lane & 7), vc = ((lane >> 4) & 1) * 8;

    // hoist Q fragments, then Q smem is recycled as K buffer 1
    uint32_t qa[4][4];
    {
        const uint32_t Ab = SQK1 + (wid * 16 + ar) * 144 + ak * 2;
        #pragma unroll
        for (int kc = 0; kc < 4; kc++) ldsm_x4(qa[kc], Ab + kc * 32);
    }
    __syncthreads();

    float o[16][4] = {};
    float rs[2] = {};

    for (int j = 0; j < 32; j++) {
        const int buf = j & 1;
        const uint32_t Kb = buf ? SQK1 : SK0;
        const uint32_t Vb = SV + buf * 34816;
        if (j < 31) {
            ldK(buf ? SK0 : SQK1, j + 1);
            ldV(SV + (buf ^ 1) * 34816, j + 1);
            CP_COMMIT();
        }
        #pragma unroll
        for (int nt = 0; nt < 8; nt++) {
            // S = Q.K^T (16m x 16n)
            float s[8] = {};
            #pragma unroll
            for (int kc = 0; kc < 4; kc++) {
                uint32_t br[4];
                ldsm_x4(br, Kb + (nt * 16 + bn) * 144 + (kc * 16 + bk2) * 2);
                mma_bf16(s,     qa[kc], br);
                mma_bf16(s + 4, qa[kc], br + 2);
            }
            // exp + rowsum + pack
            #pragma unroll
            for (int t = 0; t < 8; t++) s[t] = __expf(s[t]);
            rs[0] += s[0] + s[1] + s[4] + s[5];
            rs[1] += s[2] + s[3] + s[6] + s[7];
            uint32_t pa[4];
            pa[0] = pack_bf2(s[0], s[1]);
            pa[1] = pack_bf2(s[2], s[3]);
            pa[2] = pack_bf2(s[4], s[5]);
            pa[3] = pack_bf2(s[6], s[7]);
            // O += P.V^T over 128 c
            #pragma unroll
            for (int ct = 0; ct < 8; ct++) {
                uint32_t vr[4];
                ldsm_x4t(vr, Vb + (nt * 16 + vn) * 272 + (ct * 16 + vc) * 2);
                mma_bf16(o[ct * 2],     pa, vr);
                mma_bf16(o[ct * 2 + 1], pa, vr + 2);
            }
        }
        if (j < 31) CP_WAIT0();
        __syncthreads();
    }

    // quad-lane rowsum reduce
    float inv[2];
    #pragma unroll
    for (int h = 0; h < 2; h++) {
        float r = rs[h];
        r += __shfl_xor_sync(0xffffffffu, r, 1);
        r += __shfl_xor_sync(0xffffffffu, r, 2);
        inv[h] = 1.0f / r;
    }

    // epilogue: transpose through smem, out[b][c][m] = O/sum + x
    float* epi = reinterpret_cast<float*>(dsm);
    const int r0 = wid * 16 + (lane >> 2);
    #pragma unroll
    for (int ot = 0; ot < 16; ot++) {
        int c = ot * 8 + (lane & 3) * 2;
        epi[r0 * 129 + c]           = o[ot][0] * inv[0];
        epi[r0 * 129 + c + 1]       = o[ot][1] * inv[0];
        epi[(r0 + 8) * 129 + c]     = o[ot][2] * inv[1];
        epi[(r0 + 8) * 129 + c + 1] = o[ot][3] * inv[1];
    }
    __syncthreads();
    const float* xb = x + (size_t)b * CIN * NPIX;
    float* ob = out + (size_t)b * CIN * NPIX;
    for (int i = tid; i < 128 * 128; i += 256) {
        int c = i >> 7, m = i & 127;
        size_t gidx = (size_t)(cq * 128 + c) * NPIX + m0 + m;
        ob[gidx] = epi[m * 129 + c] + xb[gidx];
    }
}

// ---------------------------------------------------------------------------
extern "C" void kernel_launch(void* const* d_in, const int* in_sizes, int n_in,
                              void* d_out, int out_size)
{
    const float* x  = (const float*)d_in[0];
    const float* Wq = (const float*)d_in[1];
    const float* bq = (const float*)d_in[2];
    const float* Wk = (const float*)d_in[3];
    const float* bk = (const float*)d_in[4];
    const float* Wv = (const float*)d_in[5];
    const float* bv = (const float*)d_in[6];
    float* out = (float*)d_out;

    cudaFuncSetAttribute(proj_qkv_kernel, cudaFuncAttributeMaxDynamicSharedMemorySize, 73728);
    cudaFuncSetAttribute(attn_kernel,     cudaFuncAttributeMaxDynamicSharedMemorySize, 106496);

    convert_w_kernel<<<1280, 256>>>(Wq, Wk, Wv);
    transpose_x_kernel<<<dim3(NPIX / 64, CIN / 64, B), 256>>>(x);
    proj_qkv_kernel<<<dim3(NPIX / 128, 5, B), 256, 73728>>>(bq, bk, bv);
    attn_kernel<<<dim3(NPIX / 128, 4, B), 256, 106496>>>(x, out);
}

// round 7
// speedup vs baseline: 1.3548x; 1.1629x over previous
#include <cuda_runtime.h>
#include <cuda_bf16.h>
#include <cstdint>

#define NPIX 4096
#define CIN  512
#define B    4

__device__ __align__(16) __nv_bfloat16 g_xT[(size_t)B * NPIX * CIN];   // [b][n][c]
__device__ __align__(16) __nv_bfloat16 g_q [(size_t)B * NPIX * 64];    // [b][n][d]
__device__ __align__(16) __nv_bfloat16 g_k [(size_t)B * NPIX * 64];    // [b][n][d]
__device__ __align__(16) __nv_bfloat16 g_v [(size_t)B * NPIX * CIN];   // [b][n][c]
__device__ __align__(16) __nv_bfloat16 g_wqk[128 * CIN];               // [q64;k64][c]
__device__ __align__(16) __nv_bfloat16 g_wv [CIN * CIN];               // [o][c]

// ------------------------------ helpers -----------------------------------
__device__ __forceinline__ uint32_t smem_u32(const void* p) {
    uint32_t a;
    asm("{ .reg .u64 t; cvta.to.shared.u64 t, %1; cvt.u32.u64 %0, t; }" : "=r"(a) : "l"(p));
    return a;
}
__device__ __forceinline__ void ldsm_x4(uint32_t* r, uint32_t a) {
    asm volatile("ldmatrix.sync.aligned.m8n8.x4.shared.b16 {%0,%1,%2,%3}, [%4];"
        : "=r"(r[0]), "=r"(r[1]), "=r"(r[2]), "=r"(r[3]) : "r"(a));
}
__device__ __forceinline__ void ldsm_x4t(uint32_t* r, uint32_t a) {
    asm volatile("ldmatrix.sync.aligned.m8n8.x4.trans.shared.b16 {%0,%1,%2,%3}, [%4];"
        : "=r"(r[0]), "=r"(r[1]), "=r"(r[2]), "=r"(r[3]) : "r"(a));
}
__device__ __forceinline__ void mma_bf16(float* d, const uint32_t* a, const uint32_t* b) {
    asm volatile("mma.sync.aligned.m16n8k16.row.col.f32.bf16.bf16.f32 "
        "{%0,%1,%2,%3},{%4,%5,%6,%7},{%8,%9},{%0,%1,%2,%3};"
        : "+f"(d[0]), "+f"(d[1]), "+f"(d[2]), "+f"(d[3])
        : "r"(a[0]), "r"(a[1]), "r"(a[2]), "r"(a[3]), "r"(b[0]), "r"(b[1]));
}
__device__ __forceinline__ void cp16(uint32_t dst, const void* src) {
    asm volatile("cp.async.cg.shared.global [%0], [%1], 16;" :: "r"(dst), "l"(src));
}
#define CP_COMMIT() asm volatile("cp.async.commit_group;" ::: "memory")
#define CP_WAIT0()  asm volatile("cp.async.wait_group 0;" ::: "memory")
__device__ __forceinline__ uint32_t pack_bf2(float lo, float hi) {
    uint32_t u;
    asm("cvt.rn.bf16x2.f32 %0, %1, %2;" : "=r"(u) : "f"(hi), "f"(lo));
    return u;
}

// -------------------------- prep kernels ----------------------------------
__global__ void convert_w_kernel(const float* __restrict__ Wq, const float* __restrict__ Wk,
                                 const float* __restrict__ Wv) {
    int i = blockIdx.x * 256 + threadIdx.x;
    if (i < 64 * CIN) g_wqk[i] = __float2bfloat16(Wq[i]);
    else if (i < 128 * CIN) g_wqk[i] = __float2bfloat16(Wk[i - 64 * CIN]);
    else if (i < 128 * CIN + CIN * CIN) g_wv[i - 128 * CIN] = __float2bfloat16(Wv[i - 128 * CIN]);
}

__global__ __launch_bounds__(256)
void transpose_x_kernel(const float* __restrict__ x) {
    __shared__ float s[64][65];
    const int n0 = blockIdx.x * 64, c0 = blockIdx.y * 64, b = blockIdx.z;
    const float* xb = x + ((size_t)b * CIN + c0) * NPIX + n0;
    for (int i = threadIdx.x; i < 64 * 64; i += 256) {
        int c = i >> 6, n = i & 63;
        s[c][n] = xb[(size_t)c * NPIX + n];
    }
    __syncthreads();
    __nv_bfloat16* dst = g_xT + ((size_t)b * NPIX + n0) * CIN + c0;
    for (int i = threadIdx.x; i < 64 * 32; i += 256) {
        int n = i >> 5, c2 = (i & 31) * 2;
        *reinterpret_cast<__nv_bfloat162*>(dst + (size_t)n * CIN + c2) =
            __float22bfloat162_rn(make_float2(s[c2][n], s[c2 + 1][n]));
    }
}

// ---------------- fused proj: C[n(128), out(128)] = xT . W^T --------------
__global__ __launch_bounds__(256)
void proj_qkv_kernel(const float* __restrict__ bq, const float* __restrict__ bk,
                     const float* __restrict__ bv) {
    extern __shared__ char dsm[];
    const uint32_t sb = smem_u32(dsm);
    const uint32_t SA = sb, SB = sb + 36864;
    const int tid = threadIdx.x, wid = tid >> 5, lane = tid & 31;
    const int n0 = blockIdx.x * 128, chunk = blockIdx.y, b = blockIdx.z;
    const __nv_bfloat16* gA = g_xT + ((size_t)b * NPIX + n0) * CIN;
    const __nv_bfloat16* gB = (chunk == 0) ? g_wqk : (g_wv + (size_t)(chunk - 1) * 128 * CIN);

    auto ldA = [&](uint32_t dst, int kk) {
        for (int i = tid; i < 1024; i += 256) {
            int r = i >> 3, s = i & 7;
            cp16(dst + r * 144 + s * 16, gA + (size_t)r * CIN + kk * 64 + s * 8);
        }
    };
    auto ldB = [&](uint32_t dst, int kk) {
        for (int i = tid; i < 1024; i += 256) {
            int r = i >> 3, s = i & 7;
            cp16(dst + r * 144 + s * 16, gB + (size_t)r * CIN + kk * 64 + s * 8);
        }
    };
    ldA(SA, 0); ldB(SB, 0); CP_COMMIT(); CP_WAIT0(); __syncthreads();

    const int ar = (lane & 7) + ((lane >> 3) & 1) * 8, ak = ((lane >> 4) & 1) * 8;
    const int bn = ((lane >> 4) & 1) * 8 + (lane & 7), bk2 = ((lane >> 3) & 1) * 8;
    float o[16][4] = {};

    for (int kk = 0; kk < 8; kk++) {
        const int buf = kk & 1;
        if (kk < 7) { ldA(SA + (buf ^ 1) * 18432, kk + 1); ldB(SB + (buf ^ 1) * 18432, kk + 1); CP_COMMIT(); }
        const uint32_t Ab = SA + buf * 18432 + (16 * wid + ar) * 144 + ak * 2;
        const uint32_t Bb = SB + buf * 18432;
        uint32_t qa[4][4];
        #pragma unroll
        for (int kc = 0; kc < 4; kc++) ldsm_x4(qa[kc], Ab + kc * 32);
        #pragma unroll
        for (int ot2 = 0; ot2 < 8; ot2++) {
            #pragma unroll
            for (int kc = 0; kc < 4; kc++) {
                uint32_t br[4];
                ldsm_x4(br, Bb + (ot2 * 16 + bn) * 144 + (kc * 16 + bk2) * 2);
                mma_bf16(o[ot2 * 2],     qa[kc], br);
                mma_bf16(o[ot2 * 2 + 1], qa[kc], br + 2);
            }
        }
        if (kk < 7) CP_WAIT0();
        __syncthreads();
    }

    const int r0 = 16 * wid + (lane >> 2);
    if (chunk == 0) {
        #pragma unroll
        for (int ot = 0; ot < 16; ot++) {
            int oc = ot * 8 + (lane & 3) * 2;
            const float* bias = (oc < 64) ? bq : bk;
            int oo = oc & 63;
            float b0 = __ldg(bias + oo), b1 = __ldg(bias + oo + 1);
            __nv_bfloat16* base = (oc < 64) ? g_q : g_k;
            uint32_t* d0 = reinterpret_cast<uint32_t*>(base + ((size_t)b * NPIX + n0 + r0) * 64 + oo);
            uint32_t* d1 = reinterpret_cast<uint32_t*>(base + ((size_t)b * NPIX + n0 + r0 + 8) * 64 + oo);
            *d0 = pack_bf2(o[ot][0] + b0, o[ot][1] + b1);
            *d1 = pack_bf2(o[ot][2] + b0, o[ot][3] + b1);
        }
    } else {
        const int c0 = (chunk - 1) * 128;
        #pragma unroll
        for (int ot = 0; ot < 16; ot++) {
            int c = c0 + ot * 8 + (lane & 3) * 2;
            float b0 = __ldg(bv + c), b1 = __ldg(bv + c + 1);
            uint32_t* d0 = reinterpret_cast<uint32_t*>(g_v + ((size_t)b * NPIX + n0 + r0) * CIN + c);
            uint32_t* d1 = reinterpret_cast<uint32_t*>(g_v + ((size_t)b * NPIX + n0 + r0 + 8) * CIN + c);
            *d0 = pack_bf2(o[ot][0] + b0, o[ot][1] + b1);
            *d1 = pack_bf2(o[ot][2] + b0, o[ot][3] + b1);
        }
    }
}

// --------------------------- fused attention ------------------------------
// CTA: 64 m x 256 c-half x b (grid 64x2x4 = 512). 128 threads = 4 warps,
// each warp owns 16m x 256c (o = 128 fp32 regs; budget 256/thread at 2 CTA/SM).
// n-tile 64, double buffered. smem 84 KB:
//   [SQK1 9216 | SK0 9216 | SV 2x33792]; Q smem recycled as K buf 1.
// Epilogue reuses smem as f32 epi[64][257] (65792 B).
__global__ __launch_bounds__(128, 2)
void attn_kernel(const float* __restrict__ x, float* __restrict__ out) {
    extern __shared__ char dsm[];
    const uint32_t sb = smem_u32(dsm);
    const uint32_t SQK1 = sb, SK0 = sb + 9216, SV = sb + 18432;
    const int tid = threadIdx.x, wid = tid >> 5, lane = tid & 31;
    const int m0 = blockIdx.x * 64, chalf = blockIdx.y, b = blockIdx.z;

    const __nv_bfloat16* gQ = g_q + ((size_t)b * NPIX + m0) * 64;
    const __nv_bfloat16* gK = g_k + (size_t)b * NPIX * 64;
    const __nv_bfloat16* gV = g_v + (size_t)b * NPIX * CIN + chalf * 256;

    auto ldK = [&](uint32_t dst, int jj) {
        const __nv_bfloat16* src = gK + (size_t)jj * 64 * 64;
        for (int i = tid; i < 512; i += 128) {
            int r = i >> 3, s = i & 7;
            cp16(dst + r * 144 + s * 16, src + (size_t)r * 64 + s * 8);
        }
    };
    auto ldV = [&](uint32_t dst, int jj) {
        const __nv_bfloat16* src = gV + (size_t)jj * 64 * CIN;
        for (int i = tid; i < 2048; i += 128) {
            int r = i >> 5, s = i & 31;
            cp16(dst + r * 528 + s * 16, src + (size_t)r * CIN + s * 8);
        }
    };
    // prologue: Q (64m x 64d into SQK1), K0, V0
    for (int i = tid; i < 512; i += 128) {
        int r = i >> 3, s = i & 7;
        cp16(SQK1 + r * 144 + s * 16, gQ + (size_t)r * 64 + s * 8);
    }
    ldK(SK0, 0); ldV(SV, 0);
    CP_COMMIT(); CP_WAIT0(); __syncthreads();

    const int ar = (lane & 7) + ((lane >> 3) & 1) * 8, ak = ((lane >> 4) & 1) * 8;
    const int bn = ((lane >> 4) & 1) * 8 + (lane & 7), bk2 = ((lane >> 3) & 1) * 8;
    const int vn = ((lane >> 3) & 1) * 8 + (lane & 7), vc = ((lane >> 4) & 1) * 8;

    // hoist Q fragments; Q smem becomes K buffer 1
    uint32_t qa[4][4];
    {
        const uint32_t Ab = SQK1 + (wid * 16 + ar) * 144 + ak * 2;
        #pragma unroll
        for (int kc = 0; kc < 4; kc++) ldsm_x4(qa[kc], Ab + kc * 32);
    }
    __syncthreads();

    float o[32][4] = {};
    float rs[2] = {};

    for (int j = 0; j < 64; j++) {
        const int buf = j & 1;
        const uint32_t Kb = buf ? SQK1 : SK0;
        const uint32_t Vb = SV + buf * 33792;
        if (j < 63) {
            ldK(buf ? SK0 : SQK1, j + 1);
            ldV(SV + (buf ^ 1) * 33792, j + 1);
            CP_COMMIT();
        }
        #pragma unroll
        for (int nt = 0; nt < 4; nt++) {
            // S = Q.K^T (16m x 16n)
            float s[8] = {};
            #pragma unroll
            for (int kc = 0; kc < 4; kc++) {
                uint32_t br[4];
                ldsm_x4(br, Kb + (nt * 16 + bn) * 144 + (kc * 16 + bk2) * 2);
                mma_bf16(s,     qa[kc], br);
                mma_bf16(s + 4, qa[kc], br + 2);
            }
            // exp + rowsum + pack
            #pragma unroll
            for (int t = 0; t < 8; t++) s[t] = __expf(s[t]);
            rs[0] += s[0] + s[1] + s[4] + s[5];
            rs[1] += s[2] + s[3] + s[6] + s[7];
            uint32_t pa[4];
            pa[0] = pack_bf2(s[0], s[1]);
            pa[1] = pack_bf2(s[2], s[3]);
            pa[2] = pack_bf2(s[4], s[5]);
            pa[3] = pack_bf2(s[6], s[7]);
            // O += P.V^T over 256 c
            #pragma unroll
            for (int ct = 0; ct < 16; ct++) {
                uint32_t vr[4];
                ldsm_x4t(vr, Vb + (nt * 16 + vn) * 528 + (ct * 16 + vc) * 2);
                mma_bf16(o[ct * 2],     pa, vr);
                mma_bf16(o[ct * 2 + 1], pa, vr + 2);
            }
        }
        if (j < 63) CP_WAIT0();
        __syncthreads();
    }

    // quad-lane rowsum reduce
    float inv[2];
    #pragma unroll
    for (int h = 0; h < 2; h++) {
        float r = rs[h];
        r += __shfl_xor_sync(0xffffffffu, r, 1);
        r += __shfl_xor_sync(0xffffffffu, r, 2);
        inv[h] = 1.0f / r;
    }

    // epilogue: transpose through smem, out[b][c][m] = O/sum + x
    float* epi = reinterpret_cast<float*>(dsm);
    const int r0 = wid * 16 + (lane >> 2);
    #pragma unroll
    for (int ot = 0; ot < 32; ot++) {
        int c = ot * 8 + (lane & 3) * 2;
        epi[r0 * 257 + c]           = o[ot][0] * inv[0];
        epi[r0 * 257 + c + 1]       = o[ot][1] * inv[0];
        epi[(r0 + 8) * 257 + c]     = o[ot][2] * inv[1];
        epi[(r0 + 8) * 257 + c + 1] = o[ot][3] * inv[1];
    }
    __syncthreads();
    const float* xb = x + (size_t)b * CIN * NPIX;
    float* ob = out + (size_t)b * CIN * NPIX;
    for (int i = tid; i < 256 * 64; i += 128) {
        int c = i >> 6, m = i & 63;
        size_t gidx = (size_t)(chalf * 256 + c) * NPIX + m0 + m;
        ob[gidx] = epi[m * 257 + c] + xb[gidx];
    }
}

// ---------------------------------------------------------------------------
extern "C" void kernel_launch(void* const* d_in, const int* in_sizes, int n_in,
                              void* d_out, int out_size)
{
    const float* x  = (const float*)d_in[0];
    const float* Wq = (const float*)d_in[1];
    const float* bq = (const float*)d_in[2];
    const float* Wk = (const float*)d_in[3];
    const float* bk = (const float*)d_in[4];
    const float* Wv = (const float*)d_in[5];
    const float* bv = (const float*)d_in[6];
    float* out = (float*)d_out;

    cudaFuncSetAttribute(proj_qkv_kernel, cudaFuncAttributeMaxDynamicSharedMemorySize, 73728);
    cudaFuncSetAttribute(attn_kernel,     cudaFuncAttributeMaxDynamicSharedMemorySize, 86016);

    convert_w_kernel<<<1280, 256>>>(Wq, Wk, Wv);
    transpose_x_kernel<<<dim3(NPIX / 64, CIN / 64, B), 256>>>(x);
    proj_qkv_kernel<<<dim3(NPIX / 128, 5, B), 256, 73728>>>(bq, bk, bv);
    attn_kernel<<<dim3(NPIX / 64, 2, B), 128, 86016>>>(x, out);
}